// round 13
// baseline (speedup 1.0000x reference)
#include <cuda_runtime.h>
#include <math.h>
#include <stdint.h>

#define T 2048
#define ESLOTS 64
#define VOCAB 50257
#define OUTW 50348   // 2 + 64 + 25 + 50257
#define NCTA 32      // LSTM cooperative CTAs

// ---------------- static device scratch ----------------
static __device__ __align__(16) float g_X[T * 256];
static __device__ __align__(16) float g_Xp[T * 1024];
static __device__ __align__(16) float g_H[T * 256];
static __device__ __align__(16) float g_WentH[T * 256];
static __device__ __align__(16) float g_WdH[T * 256];
static __device__ __align__(16) float g_E[T * 256];   // e_cur (pre-update) per step
static __device__ __align__(16) float g_U[T * 256];   // updated entity value per step
static __device__ __align__(16) float g_V[T * 256];   // h + We@e + We_b
static __device__ int   g_last[T * ESLOTS];
static __device__ __align__(16) float g_b2[1024];
static __device__ __align__(16) float g_q[2 * 256];
static __device__ __align__(16) float g_wrow[256];
static __device__ __align__(16) float g_hbuf[2][256];  // parity-double-buffered h
static __device__ __align__(128) unsigned g_flags[32]; // one 128B line

// ---------------- helpers ----------------
__device__ __forceinline__ unsigned ld_acq(const unsigned* p) {
    unsigned v;
    asm volatile("ld.acquire.gpu.global.u32 %0, [%1];" : "=r"(v) : "l"(p) : "memory");
    return v;
}
__device__ __forceinline__ void st_rel(unsigned* p, unsigned v) {
    asm volatile("st.release.gpu.global.u32 [%0], %1;" :: "l"(p), "r"(v) : "memory");
}
__device__ __forceinline__ float ld_vol(const float* p) {
    float v;
    asm volatile("ld.volatile.global.f32 %0, [%1];" : "=f"(v) : "l"(p) : "memory");
    return v;
}
__device__ __forceinline__ float wred(float s) {
    s += __shfl_xor_sync(0xffffffffu, s, 16);
    s += __shfl_xor_sync(0xffffffffu, s, 8);
    s += __shfl_xor_sync(0xffffffffu, s, 4);
    s += __shfl_xor_sync(0xffffffffu, s, 2);
    s += __shfl_xor_sync(0xffffffffu, s, 1);
    return s;
}
// fast activations: MUFU.EX2 + fast divide, rel err ~1e-6
__device__ __forceinline__ float fsig(float x) {
    return __fdividef(1.f, 1.f + __expf(-x));
}
__device__ __forceinline__ float ftanh(float x) {
    return 1.f - __fdividef(2.f, 1.f + __expf(2.f * x));
}

// ---------------- K0: gather embeddings, reset flags + hbuf[0] ----------------
__global__ void k_gather(const int* __restrict__ tokens, const float* __restrict__ emb) {
    int t = blockIdx.x, tid = threadIdx.x;
    if (t == 0) {
        if (tid < 32) g_flags[tid] = 0u;
        g_hbuf[0][tid] = 0.f;
    }
    long long tok = tokens[t];
    g_X[(long long)t * 256 + tid] = emb[tok * 256 + tid];
}

// ---------------- K1: small precompute ----------------
__global__ void k_small(const float* __restrict__ b_ih, const float* __restrict__ b_hh,
                        const float* __restrict__ r_emb, const float* __restrict__ WrW,
                        const float* __restrict__ WentW) {
    int tid = threadIdx.x;  // 256
    for (int r = tid; r < 1024; r += 256) g_b2[r] = b_ih[r] + b_hh[r];
    for (int j = 0; j < 2; j++) {
        float s = 0.f;
        for (int k = 0; k < 256; k++) s = fmaf(r_emb[j * 256 + k], WrW[k * 256 + tid], s);
        g_q[j * 256 + tid] = s;
    }
    float s = 0.f;
    for (int j = 0; j < 256; j++) s += WentW[tid * 256 + j];
    g_wrow[tid] = s;
}

// ---------------- K2: last update step of slot i before t ----------------
__global__ void k_last(const int* __restrict__ eids) {
    __shared__ int se[T];
    int i = threadIdx.x;  // 64
    for (int j = i; j < T; j += 64) se[j] = eids[j];
    __syncthreads();
    int last = -1;
#pragma unroll 8
    for (int t = 0; t < T; t++) {
        g_last[t * ESLOTS + i] = last;
        if (se[t] == i) last = t;
    }
}

// ---------------- SGEMM: C[m,n]=sum_k A[m,k]*B[n,k] (+bias[n]) (+Add[m,n]) ----------------
// A: [M,256], B: [N,256] row-major. 128x128 tile, ktile=8, double-buffered.
__global__ void __launch_bounds__(256) sgemm256(
        const float* __restrict__ A, const float* __restrict__ B,
        const float* __restrict__ bias, const float* __restrict__ Add,
        float* __restrict__ C, int N, long long cstride, long long coff) {
    __shared__ float As[2][8][132];
    __shared__ float Bs[2][8][132];
    int tid = threadIdx.x;
    int m0 = blockIdx.x * 128;
    int n0 = blockIdx.y * 128;
    int tx = tid & 15, ty = tid >> 4;
    int lrow = tid >> 1;
    int lcg = (tid & 1) * 4;

    const float* Aptr = A + (long long)(m0 + lrow) * 256 + lcg;
    int brow = n0 + lrow;
    bool bvalid = brow < N;
    const float* Bptr = B + (long long)brow * 256 + lcg;

    float acc[8][8];
#pragma unroll
    for (int i = 0; i < 8; i++)
#pragma unroll
        for (int j = 0; j < 8; j++) acc[i][j] = 0.f;

    // stage 0
    {
        float4 a4 = *(const float4*)(Aptr);
        float4 b4 = bvalid ? *(const float4*)(Bptr) : make_float4(0.f, 0.f, 0.f, 0.f);
        As[0][lcg + 0][lrow] = a4.x; As[0][lcg + 1][lrow] = a4.y;
        As[0][lcg + 2][lrow] = a4.z; As[0][lcg + 3][lrow] = a4.w;
        Bs[0][lcg + 0][lrow] = b4.x; Bs[0][lcg + 1][lrow] = b4.y;
        Bs[0][lcg + 2][lrow] = b4.z; Bs[0][lcg + 3][lrow] = b4.w;
    }
    __syncthreads();

    int buf = 0;
    for (int k0 = 8; k0 <= 256; k0 += 8) {
        float4 na, nb;
        bool more = (k0 < 256);
        if (more) {
            na = *(const float4*)(Aptr + k0);
            nb = bvalid ? *(const float4*)(Bptr + k0) : make_float4(0.f, 0.f, 0.f, 0.f);
        }
#pragma unroll
        for (int kk = 0; kk < 8; kk++) {
            float a[8], b[8];
            *(float4*)(a)     = *(const float4*)(&As[buf][kk][ty * 8]);
            *(float4*)(a + 4) = *(const float4*)(&As[buf][kk][ty * 8 + 4]);
            *(float4*)(b)     = *(const float4*)(&Bs[buf][kk][tx * 4]);
            *(float4*)(b + 4) = *(const float4*)(&Bs[buf][kk][64 + tx * 4]);
#pragma unroll
            for (int i = 0; i < 8; i++)
#pragma unroll
                for (int j = 0; j < 8; j++) acc[i][j] = fmaf(a[i], b[j], acc[i][j]);
        }
        if (more) {
            int nbuf = buf ^ 1;
            As[nbuf][lcg + 0][lrow] = na.x; As[nbuf][lcg + 1][lrow] = na.y;
            As[nbuf][lcg + 2][lrow] = na.z; As[nbuf][lcg + 3][lrow] = na.w;
            Bs[nbuf][lcg + 0][lrow] = nb.x; Bs[nbuf][lcg + 1][lrow] = nb.y;
            Bs[nbuf][lcg + 2][lrow] = nb.z; Bs[nbuf][lcg + 3][lrow] = nb.w;
            __syncthreads();
            buf = nbuf;
        }
    }

#pragma unroll
    for (int i = 0; i < 8; i++) {
        long long m = m0 + ty * 8 + i;
        const float* addrow = Add ? (Add + m * 256) : (const float*)0;
        float* crow = C + m * cstride + coff;
#pragma unroll
        for (int j = 0; j < 8; j++) {
            int n = n0 + ((j < 4) ? (tx * 4 + j) : (64 + tx * 4 + (j - 4)));
            if (n < N) {
                float v = acc[i][j];
                if (bias) v += bias[n];
                if (addrow) v += addrow[n];
                crow[n] = v;
            }
        }
    }
}

// ---------------- K3: cooperative LSTM, 32 CTAs x 256 thr, h-exchange ----------------
// CTA k owns h[8k..8k+8) and the 32 W_hh rows {256*g + 8k + e : g<4, e<8}.
// Per step: matvec (local) -> bar -> warp0 lanes0-7: activations, h slice ->
// hbuf[(t+1)&1] -> syncwarp -> lane0 st.release flags[cta]=t+1 -> warp0 polls
// all 32 flags (one 128B acquire wavefront) -> bar. Only h (1KB) is exchanged.
// Monotonic flags + 2-deep h buffers: a CTA overwrites hbuf parity p at step
// t+2 only after all flags >= t+2, i.e. after every CTA finished reading
// parity p at step t+1. ld.volatile on h bypasses (non-coherent) L1.
__global__ void __launch_bounds__(256) k_lstm(const float* __restrict__ Xp,
                                              const float* __restrict__ Whh,
                                              float* __restrict__ Hout) {
    __shared__ float sw[32 * 256];
    __shared__ float sg[32];
    int tid = threadIdx.x;
    int cta = blockIdx.x;
    int k8 = cta * 8;
    int warp = tid >> 5, lane = tid & 31;   // 8 warps

    // load this CTA's 32 W_hh rows: local row r -> global row 256*(r>>3)+k8+(r&7)
    for (int r = warp; r < 32; r += 8) {
        const float4* src = (const float4*)(Whh + (long long)(256 * (r >> 3) + k8 + (r & 7)) * 256);
        float4* dst = (float4*)(sw + r * 256);
        for (int i = lane; i < 64; i += 32) dst[i] = src[i];
    }
    float c = 0.f;   // meaningful in warp0 lanes 0-7 only
    __syncthreads();

    for (int t = 0; t < T; t++) {
        // prefetch Xp for this warp's 4 rows (off the h-dependent path)
        float xp[4];
#pragma unroll
        for (int rr = 0; rr < 4; rr++) {
            int r = warp * 4 + rr;
            int grow = 256 * (r >> 3) + k8 + (r & 7);
            xp[rr] = __ldg(&Xp[(long long)t * 1024 + grow]);
        }
        // load h_t from global parity buffer (volatile: bypass stale L1)
        const float* hb = g_hbuf[t & 1];
        float hreg[8];
#pragma unroll
        for (int i = 0; i < 8; i++) hreg[i] = ld_vol(&hb[lane + 32 * i]);
        // matvec: 8 warps x 4 rows
#pragma unroll
        for (int rr = 0; rr < 4; rr++) {
            int r = warp * 4 + rr;
            float s = 0.f;
#pragma unroll
            for (int i = 0; i < 8; i++)
                s = fmaf(sw[r * 256 + lane + 32 * i], hreg[i], s);
            s = wred(s);
            if (lane == 0) sg[r] = s + xp[rr];
        }
        __syncthreads();
        if (warp == 0) {
            if (lane < 8) {
                float gi = sg[lane];        // g=0 rows
                float gf = sg[8 + lane];    // g=1
                float gg = sg[16 + lane];   // g=2
                float go = sg[24 + lane];   // g=3
                c = fsig(gf) * c + fsig(gi) * ftanh(gg);
                float h = fsig(go) * ftanh(c);
                g_hbuf[(t + 1) & 1][k8 + lane] = h;
                Hout[(long long)t * 256 + k8 + lane] = h;
            }
            __syncwarp();
            if (lane == 0) st_rel(&g_flags[cta], (unsigned)(t + 1));
            unsigned tgt = (unsigned)(t + 1);
            bool ok;
            do {
                unsigned v = ld_acq(&g_flags[lane]);  // 32 flags, one 128B wavefront
                ok = __all_sync(0xffffffffu, v >= tgt);
            } while (!ok);
        }
        __syncthreads();
    }
}

// ---------------- K4: entity chains, one warp per slot (64 independent chains) ----------------
__global__ void __launch_bounds__(1024) k_entity2(
        const int* __restrict__ eids, const float* __restrict__ H,
        const float* __restrict__ WdH, const float* __restrict__ ents_init,
        const float* __restrict__ Wdelta_b,
        float* __restrict__ Eout, float* __restrict__ Uout) {
    int slot = blockIdx.x * 32 + (threadIdx.x >> 5);  // 2 CTAs x 32 warps = 64 slots
    int lane = threadIdx.x & 31;
    float e[8];
#pragma unroll
    for (int i = 0; i < 8; i++) e[i] = ents_init[(long long)slot * 256 + lane + 32 * i];
    float wdb = Wdelta_b[0];

    for (int t0 = 0; t0 < T; t0 += 32) {
        int myeid = eids[t0 + lane];
        unsigned mask = __ballot_sync(0xffffffffu, myeid == slot);
        while (mask) {
            int b = __ffs(mask) - 1;
            mask &= mask - 1;
            long long tb = (long long)(t0 + b) * 256 + lane;
            float wd[8], h[8];
#pragma unroll
            for (int i = 0; i < 8; i++) wd[i] = __ldg(&WdH[tb + 32 * i]);
#pragma unroll
            for (int i = 0; i < 8; i++) h[i] = __ldg(&H[tb + 32 * i]);
            float d = 0.f;
#pragma unroll
            for (int i = 0; i < 8; i++) d = fmaf(e[i], wd[i], d);
            d = wred(d);
            float delta = fsig(d + wdb);
            float u[8], ss = 0.f;
#pragma unroll
            for (int i = 0; i < 8; i++) {
                u[i] = delta * e[i] + (1.f - delta) * h[i];
                ss = fmaf(u[i], u[i], ss);
            }
            ss = wred(ss);
            float rn = 1.f / sqrtf(ss);
#pragma unroll
            for (int i = 0; i < 8; i++) {
                Eout[tb + 32 * i] = e[i];
                float uv = u[i] * rn;
                Uout[tb + 32 * i] = uv;
                e[i] = uv;
            }
        }
    }
}

// ---------------- K5: heads -> pred_r (2), pred_e (64), pred_l (25) ----------------
__global__ void __launch_bounds__(256) k_heads(
        const float* __restrict__ ents_init, const float* __restrict__ dist_init,
        const float* __restrict__ WlenW, const float* __restrict__ Wlenb,
        const float* __restrict__ Wrb, const float* __restrict__ Wentb,
        const float* __restrict__ wdW, const float* __restrict__ wdb_,
        float* __restrict__ out) {
    __shared__ float sh[256], se[256], swt[256];
    int t = blockIdx.x;
    int tid = threadIdx.x;
    int warp = tid >> 5, lane = tid & 31;
    long long tb = (long long)t * 256;
    sh[tid] = g_H[tb + tid];
    se[tid] = g_E[tb + tid];
    swt[tid] = g_WentH[tb + tid];
    float wr[8];
#pragma unroll
    for (int i = 0; i < 8; i++) wr[i] = g_wrow[lane + 32 * i];
    __syncthreads();

    float wdw = wdW[0], wdb = wdb_[0], wentb = Wentb[0];
    float* orow = out + (long long)t * OUTW;

#pragma unroll
    for (int ssi = 0; ssi < 8; ssi++) {
        int s = warp + ssi * 8;
        int li = g_last[t * ESLOTS + s];
        const float* sv = (li < 0) ? (ents_init + (long long)s * 256)
                                   : (g_U + (long long)li * 256);
        float d1 = 0.f, d2 = 0.f;
#pragma unroll
        for (int i = 0; i < 8; i++) {
            float v = sv[lane + 32 * i];
            d1 = fmaf(v, swt[lane + 32 * i], d1);
            d2 = fmaf(v, wr[i], d2);
        }
        d1 = wred(d1);
        d2 = wred(d2);
        if (lane == 0) {
            float dist = ((li < 0) ? dist_init[s] : (float)li) - (float)t;
            orow[2 + s] = d1 + (dist * wdw + wdb) * d2 + wentb;
        }
    }

    if (warp < 2) {
        float d = 0.f;
#pragma unroll
        for (int i = 0; i < 8; i++)
            d = fmaf(g_q[warp * 256 + lane + 32 * i], sh[lane + 32 * i], d);
        d = wred(d);
        if (lane == 0) orow[warp] = d + Wrb[0];
    }

#pragma unroll
    for (int rr = 0; rr < 4; rr++) {
        int l = warp + rr * 8;
        if (l < 25) {
            float d = 0.f;
#pragma unroll
            for (int i = 0; i < 16; i++) {
                int idx = lane + 32 * i;
                float x = (idx < 256) ? sh[idx] : se[idx - 256];
                d = fmaf(WlenW[(long long)l * 512 + idx], x, d);
            }
            d = wred(d);
            if (lane == 0) orow[66 + l] = d + Wlenb[l];
        }
    }
}

// ---------------- launch ----------------
extern "C" void kernel_launch(void* const* d_in, const int* in_sizes, int n_in,
                              void* d_out, int out_size) {
    const int*   tokens  = (const int*)d_in[0];
    const int*   eids    = (const int*)d_in[1];
    const float* emb     = (const float*)d_in[2];
    const float* W_ih    = (const float*)d_in[3];
    const float* W_hh    = (const float*)d_in[4];
    const float* b_ih    = (const float*)d_in[5];
    const float* b_hh    = (const float*)d_in[6];
    const float* out_W   = (const float*)d_in[7];
    const float* out_b   = (const float*)d_in[8];
    const float* r_emb   = (const float*)d_in[9];
    const float* Wr_W    = (const float*)d_in[10];
    const float* Wr_b    = (const float*)d_in[11];
    const float* Wlen_W  = (const float*)d_in[12];
    const float* Wlen_b  = (const float*)d_in[13];
    const float* Went_W  = (const float*)d_in[14];
    const float* Went_b  = (const float*)d_in[15];
    const float* wdist_W = (const float*)d_in[16];
    const float* wdist_b = (const float*)d_in[17];
    const float* Wd_W    = (const float*)d_in[18];
    const float* Wd_b    = (const float*)d_in[19];
    const float* We_W    = (const float*)d_in[20];
    const float* We_b    = (const float*)d_in[21];
    const float* ents0   = (const float*)d_in[22];
    const float* dist0   = (const float*)d_in[23];
    float* out = (float*)d_out;

    float *gX, *gXp, *gH, *gWentH, *gWdH, *gE, *gU, *gV, *gb2;
    cudaGetSymbolAddress((void**)&gX, g_X);
    cudaGetSymbolAddress((void**)&gXp, g_Xp);
    cudaGetSymbolAddress((void**)&gH, g_H);
    cudaGetSymbolAddress((void**)&gWentH, g_WentH);
    cudaGetSymbolAddress((void**)&gWdH, g_WdH);
    cudaGetSymbolAddress((void**)&gE, g_E);
    cudaGetSymbolAddress((void**)&gU, g_U);
    cudaGetSymbolAddress((void**)&gV, g_V);
    cudaGetSymbolAddress((void**)&gb2, g_b2);

    k_gather<<<T, 256>>>(tokens, emb);
    k_small<<<1, 256>>>(b_ih, b_hh, r_emb, Wr_W, Went_W);
    k_last<<<1, ESLOTS>>>(eids);

    // Xp = X @ W_ih^T + (b_ih + b_hh)
    sgemm256<<<dim3(16, 8), 256>>>(gX, W_ih, gb2, (const float*)0, gXp,
                                   1024, 1024, 0);
    // sequential LSTM -> H (32 CTAs, h-exchange, flag barrier)
    k_lstm<<<NCTA, 256>>>(gXp, W_hh, gH);
    // WentH = H @ Went^T ; WdH = H @ Wdelta^T
    sgemm256<<<dim3(16, 2), 256>>>(gH, Went_W, (const float*)0, (const float*)0,
                                   gWentH, 256, 256, 0);
    sgemm256<<<dim3(16, 2), 256>>>(gH, Wd_W, (const float*)0, (const float*)0,
                                   gWdH, 256, 256, 0);
    // entity chains (64 warps, one per slot) -> E (pre), U (post)
    k_entity2<<<2, 1024>>>(eids, gH, gWdH, ents0, Wd_b, gE, gU);
    // V = H + E @ We^T + We_b
    sgemm256<<<dim3(16, 2), 256>>>(gE, We_W, We_b, gH, gV, 256, 256, 0);
    // heads: pred_r / pred_e / pred_l -> out cols [0,91)
    k_heads<<<T, 256>>>(ents0, dist0, Wlen_W, Wlen_b, Wr_b, Went_b,
                        wdist_W, wdist_b, out);
    // pred_x = V @ out_W^T + out_b -> out cols [91, 50348)
    sgemm256<<<dim3(16, (VOCAB + 127) / 128), 256>>>(gV, out_W, out_b,
                                                     (const float*)0, out,
                                                     VOCAB, OUTW, 91);
}

// round 16
// speedup vs baseline: 2.3282x; 2.3282x over previous
#include <cuda_runtime.h>
#include <math.h>
#include <stdint.h>

#define T 2048
#define ESLOTS 64
#define VOCAB 50257
#define OUTW 50348   // 2 + 64 + 25 + 50257
#define NLSTM 32     // LSTM cooperative CTAs
#define NBLK 16      // 2048 / 128 pipeline blocks
#define NTILE_N 393  // ceil(50257/128)
#define VOC_CTAS 111 // 148 - 32 - 2 - 1 - 2

// ---------------- static device scratch ----------------
static __device__ __align__(16) float g_X[T * 256];
static __device__ __align__(16) float g_Xp[T * 1024];
static __device__ __align__(16) float g_H[T * 256];
static __device__ __align__(16) float g_WentH[T * 256];
static __device__ __align__(16) float g_WdH[T * 256];
static __device__ __align__(16) float g_E[T * 256];
static __device__ __align__(16) float g_U[T * 256];
static __device__ __align__(16) float g_V[T * 256];
static __device__ int   g_last[T * ESLOTS];
static __device__ __align__(16) float g_b2[1024];
static __device__ __align__(16) float g_q[2 * 256];
static __device__ __align__(16) float g_wrow[256];
static __device__ float g_gates[2][1024];
static __device__ unsigned g_cnt;
static __device__ unsigned g_hprog;     // LSTM: steps completed
static __device__ unsigned g_wdf[2];    // WdH tiles done per block (2 halves)
static __device__ unsigned g_eprog;     // entity blocks done
static __device__ unsigned g_vf[2];     // V tiles done per block (2 halves)

// ---------------- helpers ----------------
__device__ __forceinline__ unsigned ld_acq(const unsigned* p) {
    unsigned v;
    asm volatile("ld.acquire.gpu.global.u32 %0, [%1];" : "=r"(v) : "l"(p) : "memory");
    return v;
}
__device__ __forceinline__ void st_rel(unsigned* p, unsigned v) {
    asm volatile("st.release.gpu.global.u32 [%0], %1;" :: "l"(p), "r"(v) : "memory");
}
__device__ __forceinline__ void red_release(unsigned* p) {
    asm volatile("red.release.gpu.global.add.u32 [%0], 1;" :: "l"(p) : "memory");
}
__device__ __forceinline__ float ld_vol(const float* p) {
    float v;
    asm volatile("ld.volatile.global.f32 %0, [%1];" : "=f"(v) : "l"(p) : "memory");
    return v;
}
__device__ __forceinline__ void st_vol(float* p, float v) {
    asm volatile("st.volatile.global.f32 [%0], %1;" :: "l"(p), "f"(v) : "memory");
}
__device__ __forceinline__ float wred(float s) {
    s += __shfl_xor_sync(0xffffffffu, s, 16);
    s += __shfl_xor_sync(0xffffffffu, s, 8);
    s += __shfl_xor_sync(0xffffffffu, s, 4);
    s += __shfl_xor_sync(0xffffffffu, s, 2);
    s += __shfl_xor_sync(0xffffffffu, s, 1);
    return s;
}
__device__ __forceinline__ float sigacc(float x) { return 1.f / (1.f + expf(-x)); }

// ---------------- K0: gather embeddings, reset all flags ----------------
__global__ void k_gather(const int* __restrict__ tokens, const float* __restrict__ emb) {
    int t = blockIdx.x, tid = threadIdx.x;
    if (t == 0 && tid == 0) {
        g_cnt = 0u; g_hprog = 0u; g_eprog = 0u;
        g_wdf[0] = g_wdf[1] = 0u; g_vf[0] = g_vf[1] = 0u;
    }
    long long tok = tokens[t];
    g_X[(long long)t * 256 + tid] = emb[tok * 256 + tid];
}

// ---------------- K1: small precompute ----------------
__global__ void k_small(const float* __restrict__ b_ih, const float* __restrict__ b_hh,
                        const float* __restrict__ r_emb, const float* __restrict__ WrW,
                        const float* __restrict__ WentW) {
    int tid = threadIdx.x;  // 256
    for (int r = tid; r < 1024; r += 256) g_b2[r] = b_ih[r] + b_hh[r];
    for (int j = 0; j < 2; j++) {
        float s = 0.f;
        for (int k = 0; k < 256; k++) s = fmaf(r_emb[j * 256 + k], WrW[k * 256 + tid], s);
        g_q[j * 256 + tid] = s;
    }
    float s = 0.f;
    for (int j = 0; j < 256; j++) s += WentW[tid * 256 + j];
    g_wrow[tid] = s;
}

// ---------------- K2: last update step of slot i before t ----------------
__global__ void k_last(const int* __restrict__ eids) {
    __shared__ int se[T];
    int i = threadIdx.x;  // 64
    for (int j = i; j < T; j += 64) se[j] = eids[j];
    __syncthreads();
    int last = -1;
#pragma unroll 8
    for (int t = 0; t < T; t++) {
        g_last[t * ESLOTS + i] = last;
        if (se[t] == i) last = t;
    }
}

// ---------------- SGEMM tile body (128x128x256), shared by all GEMM users ----------------
// C[m,n] = sum_k A[m,k]*B[n,k] (+bias[n]) (+Add[m,n]); A rows must be valid.
// sm: 2*2112 floats ( As[2][8][132], Bs[2][8][132] ).
__device__ __forceinline__ void gemm_tile(
        const float* __restrict__ A, const float* __restrict__ B,
        const float* bias, const float* Add, float* C, int N,
        long long cstride, long long coff, int m0, int n0, float* sm) {
    float* As = sm;
    float* Bs = sm + 2112;
    int tid = threadIdx.x;
    int tx = tid & 15, ty = tid >> 4;
    int lrow = tid >> 1;
    int lcg = (tid & 1) * 4;

    const float* Aptr = A + (long long)(m0 + lrow) * 256 + lcg;
    int brow = n0 + lrow;
    bool bvalid = brow < N;
    const float* Bptr = B + (long long)brow * 256 + lcg;

    float acc[8][8];
#pragma unroll
    for (int i = 0; i < 8; i++)
#pragma unroll
        for (int j = 0; j < 8; j++) acc[i][j] = 0.f;

    {
        float4 a4 = *(const float4*)(Aptr);
        float4 b4 = bvalid ? *(const float4*)(Bptr) : make_float4(0.f, 0.f, 0.f, 0.f);
        As[(lcg + 0) * 132 + lrow] = a4.x; As[(lcg + 1) * 132 + lrow] = a4.y;
        As[(lcg + 2) * 132 + lrow] = a4.z; As[(lcg + 3) * 132 + lrow] = a4.w;
        Bs[(lcg + 0) * 132 + lrow] = b4.x; Bs[(lcg + 1) * 132 + lrow] = b4.y;
        Bs[(lcg + 2) * 132 + lrow] = b4.z; Bs[(lcg + 3) * 132 + lrow] = b4.w;
    }
    __syncthreads();

    int buf = 0;
    for (int k0 = 8; k0 <= 256; k0 += 8) {
        float4 na, nb;
        bool more = (k0 < 256);
        if (more) {
            na = *(const float4*)(Aptr + k0);
            nb = bvalid ? *(const float4*)(Bptr + k0) : make_float4(0.f, 0.f, 0.f, 0.f);
        }
#pragma unroll
        for (int kk = 0; kk < 8; kk++) {
            float a[8], b[8];
            *(float4*)(a)     = *(const float4*)(&As[(buf * 8 + kk) * 132 + ty * 8]);
            *(float4*)(a + 4) = *(const float4*)(&As[(buf * 8 + kk) * 132 + ty * 8 + 4]);
            *(float4*)(b)     = *(const float4*)(&Bs[(buf * 8 + kk) * 132 + tx * 4]);
            *(float4*)(b + 4) = *(const float4*)(&Bs[(buf * 8 + kk) * 132 + 64 + tx * 4]);
#pragma unroll
            for (int i = 0; i < 8; i++)
#pragma unroll
                for (int j = 0; j < 8; j++) acc[i][j] = fmaf(a[i], b[j], acc[i][j]);
        }
        if (more) {
            int nbuf = buf ^ 1;
            As[(nbuf * 8 + lcg + 0) * 132 + lrow] = na.x;
            As[(nbuf * 8 + lcg + 1) * 132 + lrow] = na.y;
            As[(nbuf * 8 + lcg + 2) * 132 + lrow] = na.z;
            As[(nbuf * 8 + lcg + 3) * 132 + lrow] = na.w;
            Bs[(nbuf * 8 + lcg + 0) * 132 + lrow] = nb.x;
            Bs[(nbuf * 8 + lcg + 1) * 132 + lrow] = nb.y;
            Bs[(nbuf * 8 + lcg + 2) * 132 + lrow] = nb.z;
            Bs[(nbuf * 8 + lcg + 3) * 132 + lrow] = nb.w;
            __syncthreads();
            buf = nbuf;
        }
    }

#pragma unroll
    for (int i = 0; i < 8; i++) {
        long long m = m0 + ty * 8 + i;
        const float* addrow = Add ? (Add + m * 256) : (const float*)0;
        float* crow = C + m * cstride + coff;
#pragma unroll
        for (int j = 0; j < 8; j++) {
            int n = n0 + ((j < 4) ? (tx * 4 + j) : (64 + tx * 4 + (j - 4)));
            if (n < N) {
                float v = acc[i][j];
                if (bias) v += bias[n];
                if (addrow) v += addrow[n];
                crow[n] = v;
            }
        }
    }
}

// standalone SGEMM kernel (prologue Xp, post WentH)
__global__ void __launch_bounds__(256) sgemm256(
        const float* __restrict__ A, const float* __restrict__ B,
        const float* bias, const float* Add, float* C, int N,
        long long cstride, long long coff) {
    __shared__ float sm[2 * 2112];
    gemm_tile(A, B, bias, Add, C, N, cstride, coff,
              blockIdx.x * 128, blockIdx.y * 128, sm);
}

// ---------------- fused persistent kernel: 148 CTAs x 256 thr ----------------
// roles: [0,32) LSTM | [32,34) WdH gemm | 34 entity chain | [35,37) V gemm | [37,148) vocab
__global__ void __launch_bounds__(256) k_fused(
        const float* __restrict__ Xp, const float* __restrict__ Whh,
        const int* __restrict__ eids, const float* __restrict__ WdW,
        const float* __restrict__ Wdb, const float* __restrict__ ents0,
        const float* __restrict__ WeW, const float* __restrict__ Web,
        const float* __restrict__ outW, const float* __restrict__ outb,
        float* __restrict__ out) {
    extern __shared__ float dsm[];
    int cta = blockIdx.x;
    int tid = threadIdx.x;
    int warp = tid >> 5, lane = tid & 31;

    if (cta < NLSTM) {
        // ======== LSTM (R8-proven) ========
        float* sw = dsm;            // 32*256
        float* sh = dsm + 32 * 256; // 256
        int r0 = cta * 32;
        const float4* src = (const float4*)(Whh + (long long)r0 * 256);
        float4* dst = (float4*)sw;
        for (int i = tid; i < 32 * 256 / 4; i += 256) dst[i] = src[i];
        sh[tid] = 0.f;
        float c = 0.f;
        __syncthreads();
        for (int t = 0; t < T; t++) {
            float xp[4];
#pragma unroll
            for (int rr = 0; rr < 4; rr++)
                xp[rr] = __ldg(&Xp[(long long)t * 1024 + r0 + warp * 4 + rr]);
            float hreg[8];
#pragma unroll
            for (int i = 0; i < 8; i++) hreg[i] = sh[lane + 32 * i];
            float* gbuf = g_gates[t & 1];
#pragma unroll
            for (int rr = 0; rr < 4; rr++) {
                int rl = warp * 4 + rr;
                float s = 0.f;
#pragma unroll
                for (int i = 0; i < 8; i++)
                    s = fmaf(sw[rl * 256 + lane + 32 * i], hreg[i], s);
                s = wred(s);
                if (lane == 0) st_vol(&gbuf[r0 + rl], s + xp[rr]);
            }
            __syncthreads();
            if (tid == 0) {
                red_release(&g_cnt);
                unsigned target = (unsigned)NLSTM * (unsigned)(t + 1);
                while (ld_acq(&g_cnt) < target) {}
            }
            __syncthreads();
            float gi = ld_vol(&gbuf[tid]);
            float gf = ld_vol(&gbuf[256 + tid]);
            float gg = ld_vol(&gbuf[512 + tid]);
            float go = ld_vol(&gbuf[768 + tid]);
            c = sigacc(gf) * c + sigacc(gi) * tanhf(gg);
            float h = sigacc(go) * tanhf(c);
            sh[tid] = h;
            if (cta == 0) g_H[(long long)t * 256 + tid] = h;
            __syncthreads();
            if (cta == 0 && tid == 0) st_rel(&g_hprog, (unsigned)(t + 1));
        }
    } else if (cta < 34) {
        // ======== WdH = H_blk @ Wd^T (2 CTAs, one 128x128 half each) ========
        int half = cta - 32;
        for (int b = 0; b < NBLK; b++) {
            if (tid == 0)
                while (ld_acq(&g_hprog) < 128u * (unsigned)(b + 1)) __nanosleep(64);
            __syncthreads();
            gemm_tile(g_H, WdW, (const float*)0, (const float*)0, g_WdH,
                      256, 256, 0, b * 128, half * 128, dsm);
            __syncthreads();
            if (tid == 0) st_rel(&g_wdf[half], (unsigned)(b + 1));
        }
    } else if (cta == 34) {
        // ======== entity chain (sequential within block) ========
        float* tab = dsm;            // 64*256
        float* red = dsm + 64 * 256; // 16
        for (int i = tid; i < ESLOTS * 256; i += 256) tab[i] = ents0[i];
        float wdb = Wdb[0];
        __syncthreads();
        for (int b = 0; b < NBLK; b++) {
            if (tid == 0)
                while (ld_acq(&g_wdf[0]) < (unsigned)(b + 1) ||
                       ld_acq(&g_wdf[1]) < (unsigned)(b + 1)) __nanosleep(64);
            __syncthreads();
            for (int t = b * 128; t < (b + 1) * 128; t++) {
                int eid = __ldg(&eids[t]);
                long long tb = (long long)t * 256 + tid;
                float e = tab[eid * 256 + tid];
                float wd = g_WdH[tb];
                float h = g_H[tb];
                g_E[tb] = e;
                float p = wred(e * wd);
                if ((tid & 31) == 0) red[tid >> 5] = p;
                __syncthreads();
                if (tid < 32) {
                    float v = (tid < 8) ? red[tid] : 0.f;
                    v = wred(v);
                    if (tid == 0) red[8] = v;
                }
                __syncthreads();
                float delta = sigacc(red[8] + wdb);
                float u = delta * e + (1.f - delta) * h;
                float q = wred(u * u);
                __syncthreads();  // red[0..7] reuse
                if ((tid & 31) == 0) red[tid >> 5] = q;
                __syncthreads();
                if (tid < 32) {
                    float v = (tid < 8) ? red[tid] : 0.f;
                    v = wred(v);
                    if (tid == 0) red[8] = 1.f / sqrtf(v);
                }
                __syncthreads();
                u *= red[8];
                tab[eid * 256 + tid] = u;
                g_U[tb] = u;
                __syncthreads();
            }
            if (tid == 0) st_rel(&g_eprog, (unsigned)(b + 1));
        }
    } else if (cta < 37) {
        // ======== V = H + E_blk @ We^T + We_b (2 CTAs) ========
        int half = cta - 35;
        for (int b = 0; b < NBLK; b++) {
            if (tid == 0)
                while (ld_acq(&g_eprog) < (unsigned)(b + 1)) __nanosleep(64);
            __syncthreads();
            gemm_tile(g_E, WeW, Web, g_H, g_V,
                      256, 256, 0, b * 128, half * 128, dsm);
            __syncthreads();
            if (tid == 0) st_rel(&g_vf[half], (unsigned)(b + 1));
        }
    } else {
        // ======== vocab tiles, m-major streaming ========
        int vc = cta - 37;
        for (int idx = vc; idx < NBLK * NTILE_N; idx += VOC_CTAS) {
            int m = idx / NTILE_N;
            int n = idx % NTILE_N;
            if (tid == 0)
                while (ld_acq(&g_vf[0]) < (unsigned)(m + 1) ||
                       ld_acq(&g_vf[1]) < (unsigned)(m + 1)) __nanosleep(128);
            __syncthreads();
            gemm_tile(g_V, outW, outb, (const float*)0, out,
                      VOCAB, OUTW, 91, m * 128, n * 128, dsm);
            __syncthreads();
        }
    }
}

// ---------------- K5: heads -> pred_r (2), pred_e (64), pred_l (25) ----------------
__global__ void __launch_bounds__(256) k_heads(
        const float* __restrict__ ents_init, const float* __restrict__ dist_init,
        const float* __restrict__ WlenW, const float* __restrict__ Wlenb,
        const float* __restrict__ Wrb, const float* __restrict__ Wentb,
        const float* __restrict__ wdW, const float* __restrict__ wdb_,
        float* __restrict__ out) {
    __shared__ float sh[256], se[256], swt[256];
    int t = blockIdx.x;
    int tid = threadIdx.x;
    int warp = tid >> 5, lane = tid & 31;
    long long tb = (long long)t * 256;
    sh[tid] = g_H[tb + tid];
    se[tid] = g_E[tb + tid];
    swt[tid] = g_WentH[tb + tid];
    float wr[8];
#pragma unroll
    for (int i = 0; i < 8; i++) wr[i] = g_wrow[lane + 32 * i];
    __syncthreads();

    float wdw = wdW[0], wdb = wdb_[0], wentb = Wentb[0];
    float* orow = out + (long long)t * OUTW;

#pragma unroll
    for (int ssi = 0; ssi < 8; ssi++) {
        int s = warp + ssi * 8;
        int li = g_last[t * ESLOTS + s];
        const float* sv = (li < 0) ? (ents_init + (long long)s * 256)
                                   : (g_U + (long long)li * 256);
        float d1 = 0.f, d2 = 0.f;
#pragma unroll
        for (int i = 0; i < 8; i++) {
            float v = sv[lane + 32 * i];
            d1 = fmaf(v, swt[lane + 32 * i], d1);
            d2 = fmaf(v, wr[i], d2);
        }
        d1 = wred(d1);
        d2 = wred(d2);
        if (lane == 0) {
            float dist = ((li < 0) ? dist_init[s] : (float)li) - (float)t;
            orow[2 + s] = d1 + (dist * wdw + wdb) * d2 + wentb;
        }
    }

    if (warp < 2) {
        float d = 0.f;
#pragma unroll
        for (int i = 0; i < 8; i++)
            d = fmaf(g_q[warp * 256 + lane + 32 * i], sh[lane + 32 * i], d);
        d = wred(d);
        if (lane == 0) orow[warp] = d + Wrb[0];
    }

#pragma unroll
    for (int rr = 0; rr < 4; rr++) {
        int l = warp + rr * 8;
        if (l < 25) {
            float d = 0.f;
#pragma unroll
            for (int i = 0; i < 16; i++) {
                int idx = lane + 32 * i;
                float x = (idx < 256) ? sh[idx] : se[idx - 256];
                d = fmaf(WlenW[(long long)l * 512 + idx], x, d);
            }
            d = wred(d);
            if (lane == 0) orow[66 + l] = d + Wlenb[l];
        }
    }
}

// ---------------- launch ----------------
extern "C" void kernel_launch(void* const* d_in, const int* in_sizes, int n_in,
                              void* d_out, int out_size) {
    const int*   tokens  = (const int*)d_in[0];
    const int*   eids    = (const int*)d_in[1];
    const float* emb     = (const float*)d_in[2];
    const float* W_ih    = (const float*)d_in[3];
    const float* W_hh    = (const float*)d_in[4];
    const float* b_ih    = (const float*)d_in[5];
    const float* b_hh    = (const float*)d_in[6];
    const float* out_W   = (const float*)d_in[7];
    const float* out_b   = (const float*)d_in[8];
    const float* r_emb   = (const float*)d_in[9];
    const float* Wr_W    = (const float*)d_in[10];
    const float* Wr_b    = (const float*)d_in[11];
    const float* Wlen_W  = (const float*)d_in[12];
    const float* Wlen_b  = (const float*)d_in[13];
    const float* Went_W  = (const float*)d_in[14];
    const float* Went_b  = (const float*)d_in[15];
    const float* wdist_W = (const float*)d_in[16];
    const float* wdist_b = (const float*)d_in[17];
    const float* Wd_W    = (const float*)d_in[18];
    const float* Wd_b    = (const float*)d_in[19];
    const float* We_W    = (const float*)d_in[20];
    const float* We_b    = (const float*)d_in[21];
    const float* ents0   = (const float*)d_in[22];
    const float* dist0   = (const float*)d_in[23];
    float* out = (float*)d_out;

    float *gX, *gXp, *gH, *gWentH, *gb2;
    cudaGetSymbolAddress((void**)&gX, g_X);
    cudaGetSymbolAddress((void**)&gXp, g_Xp);
    cudaGetSymbolAddress((void**)&gH, g_H);
    cudaGetSymbolAddress((void**)&gWentH, g_WentH);
    cudaGetSymbolAddress((void**)&gb2, g_b2);

    // dyn smem: max(entity 64K*4+64, LSTM 33KB, gemm 16.9KB) = 65.6KB
    const int fused_smem = (64 * 256 + 16) * 4;
    cudaFuncSetAttribute(k_fused, cudaFuncAttributeMaxDynamicSharedMemorySize,
                         fused_smem);

    k_gather<<<T, 256>>>(tokens, emb);
    k_small<<<1, 256>>>(b_ih, b_hh, r_emb, Wr_W, Went_W);
    k_last<<<1, ESLOTS>>>(eids);

    // Xp = X @ W_ih^T + (b_ih + b_hh)
    sgemm256<<<dim3(16, 8), 256>>>(gX, W_ih, gb2, (const float*)0, gXp,
                                   1024, 1024, 0);
    // fused: LSTM + streaming WdH/entity/V/vocab
    k_fused<<<148, 256, fused_smem>>>(gXp, W_hh, eids, Wd_W, Wd_b, ents0,
                                      We_W, We_b, out_W, out_b, out);
    // WentH = H @ Went^T (for heads)
    sgemm256<<<dim3(16, 2), 256>>>(gH, Went_W, (const float*)0, (const float*)0,
                                   gWentH, 256, 256, 0);
    // heads: pred_r / pred_e / pred_l -> out cols [0,91)
    k_heads<<<T, 256>>>(ents0, dist0, Wlen_W, Wlen_b, Wr_b, Went_b,
                        wdist_W, wdist_b, out);
}